// round 1
// baseline (speedup 1.0000x reference)
#include <cuda_runtime.h>
#include <cuda_bf16.h>

// CosSimilarity: out[n][m] = (x[n]/||x[n]||) . (y[m]/||y[m]||) / 0.05
// N = M = 4096, D = 1024, all fp32.
//
// Round 1: fused-norm fp32 SGEMM baseline.
//  kernel 1: per-row L2 normalize (1/TEMP folded into x side) -> __device__ scratch
//  kernel 2: classic 128x128x16 SGEMM with 8x8 register tiles.

#define NROWS 4096
#define DDIM  1024

__device__ float g_xn[NROWS * DDIM];  // normalized x, pre-scaled by 1/TEMP
__device__ float g_yn[NROWS * DDIM];  // normalized y

// ---------------------------------------------------------------------------
// Kernel 1: row normalization. One block (256 threads) per row; 8192 rows.
// Each thread owns exactly one float4 (256*4 = 1024 = DDIM).
// ---------------------------------------------------------------------------
__global__ void norm_kernel(const float* __restrict__ x,
                            const float* __restrict__ y) {
    int row = blockIdx.x;              // 0..8191
    const float4* src;
    float4* dst;
    float extra;
    if (row < NROWS) {
        src = (const float4*)(x + (size_t)row * DDIM);
        dst = (float4*)(g_xn + (size_t)row * DDIM);
        extra = 20.0f;                 // 1 / TEMP
    } else {
        int r = row - NROWS;
        src = (const float4*)(y + (size_t)r * DDIM);
        dst = (float4*)(g_yn + (size_t)r * DDIM);
        extra = 1.0f;
    }

    int t = threadIdx.x;               // 0..255
    float4 v = src[t];
    float ss = v.x * v.x + v.y * v.y + v.z * v.z + v.w * v.w;

    #pragma unroll
    for (int o = 16; o > 0; o >>= 1)
        ss += __shfl_xor_sync(0xffffffffu, ss, o);

    __shared__ float warp_ss[8];
    __shared__ float s_inv;
    if ((t & 31) == 0) warp_ss[t >> 5] = ss;
    __syncthreads();
    if (t == 0) {
        float tot = 0.0f;
        #pragma unroll
        for (int i = 0; i < 8; i++) tot += warp_ss[i];
        s_inv = extra / fmaxf(sqrtf(tot), 1e-8f);
    }
    __syncthreads();

    float inv = s_inv;
    v.x *= inv; v.y *= inv; v.z *= inv; v.w *= inv;
    dst[t] = v;
}

// ---------------------------------------------------------------------------
// Kernel 2: SGEMM  C[n][m] = sum_d xn[n][d] * yn[m][d]
// Both operands K-contiguous (row-major [4096,1024]) -> "NT" gemm.
// BM=BN=128, BK=16, 256 threads, each thread computes an 8x8 tile.
// ---------------------------------------------------------------------------
#define BM 128
#define BN 128
#define BK 16
#define TM 8
#define TN 8

__global__ __launch_bounds__(256)
void sgemm_kernel(float* __restrict__ C) {
    __shared__ float As[BK][BM];
    __shared__ float Bs[BK][BN];

    const int tid = threadIdx.x;       // 0..255
    const int tx  = tid & 15;          // 0..15  -> N direction
    const int ty  = tid >> 4;          // 0..15  -> M direction

    const int rowA = blockIdx.y * BM;  // x rows
    const int rowB = blockIdx.x * BN;  // y rows

    const float* A = g_xn;
    const float* B = g_yn;

    float acc[TM][TN];
    #pragma unroll
    for (int i = 0; i < TM; i++)
        #pragma unroll
        for (int j = 0; j < TN; j++)
            acc[i][j] = 0.0f;

    // tile load plan: 128 rows x 16 cols = 512 float4s per operand;
    // 256 threads x 2 float4s each.
    const int la = tid * 2;

    for (int k0 = 0; k0 < DDIM; k0 += BK) {
        #pragma unroll
        for (int i = 0; i < 2; i++) {
            int idx = la + i;          // 0..511
            int r   = idx >> 2;        // tile row 0..127
            int c4  = idx & 3;         // float4 index within the 16-wide k slice

            float4 va = *(const float4*)(A + (size_t)(rowA + r) * DDIM + k0 + c4 * 4);
            As[c4 * 4 + 0][r] = va.x;
            As[c4 * 4 + 1][r] = va.y;
            As[c4 * 4 + 2][r] = va.z;
            As[c4 * 4 + 3][r] = va.w;

            float4 vb = *(const float4*)(B + (size_t)(rowB + r) * DDIM + k0 + c4 * 4);
            Bs[c4 * 4 + 0][r] = vb.x;
            Bs[c4 * 4 + 1][r] = vb.y;
            Bs[c4 * 4 + 2][r] = vb.z;
            Bs[c4 * 4 + 3][r] = vb.w;
        }
        __syncthreads();

        #pragma unroll
        for (int kk = 0; kk < BK; kk++) {
            float a[TM], b[TN];
            #pragma unroll
            for (int i = 0; i < 4; i++) {
                float4 a4 = *(const float4*)&As[kk][ty * TM + i * 4 - i * 4]; // placeholder avoided below
                (void)a4;
                break;
            }
            // vectorized smem reads (two float4 per operand)
            float4 a0 = *(const float4*)&As[kk][ty * TM];
            float4 a1 = *(const float4*)&As[kk][ty * TM + 4];
            float4 b0 = *(const float4*)&Bs[kk][tx * TN];
            float4 b1 = *(const float4*)&Bs[kk][tx * TN + 4];
            a[0]=a0.x; a[1]=a0.y; a[2]=a0.z; a[3]=a0.w;
            a[4]=a1.x; a[5]=a1.y; a[6]=a1.z; a[7]=a1.w;
            b[0]=b0.x; b[1]=b0.y; b[2]=b0.z; b[3]=b0.w;
            b[4]=b1.x; b[5]=b1.y; b[6]=b1.z; b[7]=b1.w;

            #pragma unroll
            for (int i = 0; i < TM; i++)
                #pragma unroll
                for (int j = 0; j < TN; j++)
                    acc[i][j] += a[i] * b[j];
        }
        __syncthreads();
    }

    #pragma unroll
    for (int i = 0; i < TM; i++) {
        float4* cp = (float4*)(C + (size_t)(rowA + ty * TM + i) * NROWS + rowB + tx * TN);
        cp[0] = make_float4(acc[i][0], acc[i][1], acc[i][2], acc[i][3]);
        cp[1] = make_float4(acc[i][4], acc[i][5], acc[i][6], acc[i][7]);
    }
}

// ---------------------------------------------------------------------------
extern "C" void kernel_launch(void* const* d_in, const int* in_sizes, int n_in,
                              void* d_out, int out_size) {
    const float* x = (const float*)d_in[0];
    const float* y = (const float*)d_in[1];
    float* out = (float*)d_out;

    norm_kernel<<<2 * NROWS, 256>>>(x, y);

    dim3 grid(NROWS / BN, NROWS / BM);
    sgemm_kernel<<<grid, 256>>>(out);
}

// round 3
// speedup vs baseline: 7.2268x; 7.2268x over previous
#include <cuda_runtime.h>
#include <cuda_fp16.h>
#include <cstdint>

// CosSimilarity via fp16 mma.sync (legacy HMMA — tcgen05 'a'-features unavailable:
// harness ptxas targets plain sm_103).
//  K1: normalize rows (x side pre-scaled by 1/TEMP=20) -> fp16 scratch.
//  K2: C[4096,4096] = Xh @ Yh^T. BM=BN=128, BK=64, 4-stage cp.async pipeline,
//      8 warps (4x2), warp tile 32x64, m16n8k16 HMMA, fp32 accum.

#define NROWS 4096
#define DDIM  1024
#define BM 128
#define BN 128
#define BK 64
#define NSTAGE 4
#define KITERS (DDIM / BK)              // 16
#define STAGE_BYTES ((BM + BN) * 128)   // 32 KB
#define SMEM_DYN (NSTAGE * STAGE_BYTES) // 128 KB

__device__ __align__(1024) __half g_xh[NROWS * DDIM];
__device__ __align__(1024) __half g_yh[NROWS * DDIM];

__device__ __forceinline__ uint32_t smem_u32(const void* p) {
    uint32_t a;
    asm("{ .reg .u64 t; cvta.to.shared.u64 t, %1; cvt.u32.u64 %0, t; }" : "=r"(a) : "l"(p));
    return a;
}

#define CP_ASYNC16(dst, src) \
    asm volatile("cp.async.cg.shared.global [%0], [%1], 16;" :: "r"(dst), "l"(src))
#define CP_COMMIT() asm volatile("cp.async.commit_group;" ::: "memory")
#define CP_WAIT2()  asm volatile("cp.async.wait_group 2;" ::: "memory")

__device__ __forceinline__ uint32_t swz(uint32_t off) {
    return off ^ ((off >> 3) & 0x70);
}

__device__ __forceinline__ void ldsm_x4(uint32_t* r, uint32_t addr) {
    asm volatile("ldmatrix.sync.aligned.m8n8.x4.shared.b16 {%0,%1,%2,%3}, [%4];"
                 : "=r"(r[0]), "=r"(r[1]), "=r"(r[2]), "=r"(r[3]) : "r"(addr));
}

__device__ __forceinline__ void mma16816(float* c, const uint32_t* a, const uint32_t* b) {
    asm volatile(
        "mma.sync.aligned.m16n8k16.row.col.f32.f16.f16.f32 "
        "{%0,%1,%2,%3}, {%4,%5,%6,%7}, {%8,%9}, {%0,%1,%2,%3};"
        : "+f"(c[0]), "+f"(c[1]), "+f"(c[2]), "+f"(c[3])
        : "r"(a[0]), "r"(a[1]), "r"(a[2]), "r"(a[3]), "r"(b[0]), "r"(b[1]));
}

// ---------------------------------------------------------------------------
// Kernel 1: row normalization -> fp16 (one 256-thread block per row)
// ---------------------------------------------------------------------------
__global__ void norm_kernel(const float* __restrict__ x, const float* __restrict__ y) {
    int row = blockIdx.x;
    const float4* src; __half2* dst; float extra;
    if (row < NROWS) {
        src = (const float4*)(x + (size_t)row * DDIM);
        dst = (__half2*)(g_xh + (size_t)row * DDIM);
        extra = 20.0f;                  // 1/TEMP folded into x side
    } else {
        int r = row - NROWS;
        src = (const float4*)(y + (size_t)r * DDIM);
        dst = (__half2*)(g_yh + (size_t)r * DDIM);
        extra = 1.0f;
    }
    int t = threadIdx.x;
    float4 v = src[t];
    float ss = v.x * v.x + v.y * v.y + v.z * v.z + v.w * v.w;
    #pragma unroll
    for (int o = 16; o > 0; o >>= 1) ss += __shfl_xor_sync(0xffffffffu, ss, o);

    __shared__ float wss[8];
    __shared__ float sinv;
    if ((t & 31) == 0) wss[t >> 5] = ss;
    __syncthreads();
    if (t == 0) {
        float tot = 0.0f;
        #pragma unroll
        for (int i = 0; i < 8; i++) tot += wss[i];
        sinv = extra / fmaxf(sqrtf(tot), 1e-8f);
    }
    __syncthreads();
    float inv = sinv;
    dst[2 * t]     = __floats2half2_rn(v.x * inv, v.y * inv);
    dst[2 * t + 1] = __floats2half2_rn(v.z * inv, v.w * inv);
}

// ---------------------------------------------------------------------------
// Kernel 2: HMMA GEMM
// ---------------------------------------------------------------------------
__global__ void __launch_bounds__(256) gemm_kernel(float* __restrict__ C) {
    extern __shared__ __align__(1024) char smem[];
    const uint32_t smem_base = smem_u32(smem);
    const int tid = threadIdx.x;
    const int wid = tid >> 5;
    const int lid = tid & 31;
    const int rowA0 = blockIdx.y * BM;   // x rows
    const int rowB0 = blockIdx.x * BN;   // y rows

    const int wm = wid & 3;              // m band (32 rows each)
    const int wn = wid >> 2;             // n band (64 cols each)

    // ldmatrix lane geometry
    const int g   = lid >> 3;
    const int rin = lid & 7;
    const int a_m  = (g & 1) * 8 + rin;  // row within 16-row A tile
    const int a_kb = (g >> 1) * 16;      // byte offset within k16 (0/16)
    const int b_n  = (g >> 1) * 8 + rin; // row within 16-row B tile pair
    const int b_kb = (g & 1) * 16;

    uint32_t a_rowoff[2], b_rowoff[4];
    #pragma unroll
    for (int t = 0; t < 2; t++)
        a_rowoff[t] = (uint32_t)(wm * 32 + t * 16 + a_m) * 128;
    #pragma unroll
    for (int p = 0; p < 4; p++)
        b_rowoff[p] = (uint32_t)(BM + wn * 64 + p * 16 + b_n) * 128;

    const char* agbase = (const char*)(g_xh + (size_t)rowA0 * DDIM);
    const char* bgbase = (const char*)(g_yh + (size_t)rowB0 * DDIM);

    // Stage loader: 256 rows x 128B = 2048 16B chunks, 8 per thread.
    auto load_stage = [&](int sbuf, int kidx) {
        uint32_t sbase = smem_base + sbuf * STAGE_BYTES;
        const char* ag = agbase + kidx * (BK * 2);
        const char* bg = bgbase + kidx * (BK * 2);
        #pragma unroll
        for (int k = 0; k < 8; k++) {
            int i = tid + k * 256;
            int r = (i >> 3) & 127;
            int c = (i & 7) * 16;
            uint32_t off = swz((uint32_t)((i < 1024 ? r : BM + r) * 128 + c));
            const char* src = (i < 1024 ? ag : bg) + (size_t)r * (DDIM * 2) + c;
            CP_ASYNC16(sbase + off, src);
        }
        CP_COMMIT();
    };

    float acc[2][8][4];
    #pragma unroll
    for (int mt = 0; mt < 2; mt++)
        #pragma unroll
        for (int nt = 0; nt < 8; nt++)
            #pragma unroll
            for (int q = 0; q < 4; q++)
                acc[mt][nt][q] = 0.0f;

    // Prologue: stages 0..2
    #pragma unroll
    for (int s = 0; s < NSTAGE - 1; s++) load_stage(s, s);

    for (int it = 0; it < KITERS; ++it) {
        CP_WAIT2();            // stage `it` resident (<=2 newer groups in flight)
        __syncthreads();       // also protects buffer (it+3)&3 from early rewrite

        int j = it + (NSTAGE - 1);
        if (j < KITERS) load_stage(j & 3, j);
        else            CP_COMMIT();          // keep group accounting uniform

        const uint32_t sbase = smem_base + (it & 3) * STAGE_BYTES;
        #pragma unroll
        for (int ks = 0; ks < 4; ks++) {
            const uint32_t kb = ks * 32;
            uint32_t a[2][4];
            #pragma unroll
            for (int t = 0; t < 2; t++)
                ldsm_x4(a[t], sbase + swz(a_rowoff[t] + kb + a_kb));
            uint32_t b[8][2];
            #pragma unroll
            for (int p = 0; p < 4; p++) {
                uint32_t r[4];
                ldsm_x4(r, sbase + swz(b_rowoff[p] + kb + b_kb));
                b[2 * p][0] = r[0]; b[2 * p][1] = r[1];
                b[2 * p + 1][0] = r[2]; b[2 * p + 1][1] = r[3];
            }
            #pragma unroll
            for (int mt = 0; mt < 2; mt++)
                #pragma unroll
                for (int nt = 0; nt < 8; nt++)
                    mma16816(acc[mt][nt], a[mt], b[nt]);
        }
    }

    // Epilogue: direct register -> gmem (float2, 32B sectors fully used)
    const int crow = rowA0 + wm * 32 + (lid >> 2);
    const int ccol = rowB0 + wn * 64 + (lid & 3) * 2;
    #pragma unroll
    for (int mt = 0; mt < 2; mt++) {
        #pragma unroll
        for (int nt = 0; nt < 8; nt++) {
            float* p0 = C + (size_t)(crow + mt * 16) * NROWS + ccol + nt * 8;
            float* p1 = p0 + 8 * NROWS;
            *(float2*)p0 = make_float2(acc[mt][nt][0], acc[mt][nt][1]);
            *(float2*)p1 = make_float2(acc[mt][nt][2], acc[mt][nt][3]);
        }
    }
}

// ---------------------------------------------------------------------------
extern "C" void kernel_launch(void* const* d_in, const int* in_sizes, int n_in,
                              void* d_out, int out_size) {
    const float* x = (const float*)d_in[0];
    const float* y = (const float*)d_in[1];
    float* out = (float*)d_out;

    cudaFuncSetAttribute(gemm_kernel, cudaFuncAttributeMaxDynamicSharedMemorySize, SMEM_DYN);

    norm_kernel<<<2 * NROWS, 256>>>(x, y);

    dim3 grid(NROWS / BN, NROWS / BM);   // (32, 32)
    gemm_kernel<<<grid, 256, SMEM_DYN>>>(out);
}

// round 4
// speedup vs baseline: 8.1118x; 1.1224x over previous
#include <cuda_runtime.h>
#include <cuda_fp16.h>
#include <cstdint>

// CosSimilarity via fp16 mma.sync (legacy HMMA; tcgen05 unavailable: harness
// ptxas targets plain sm_103).
//  K1: normalize rows (x side pre-scaled by 1/TEMP=20) -> fp16 scratch.
//  K2: C = Xh @ Yh^T. BM=BN=128, BK=64, 3-stage cp.async pipeline (96KB smem
//      -> 2 CTAs/SM), 8 warps (4x2), warp tile 32x64, m16n8k16, fp32 accum.

#define NROWS 4096
#define DDIM  1024
#define BM 128
#define BN 128
#define BK 64
#define NSTAGE 3
#define KITERS (DDIM / BK)              // 16
#define STAGE_BYTES ((BM + BN) * 128)   // 32 KB
#define SMEM_DYN (NSTAGE * STAGE_BYTES) // 96 KB

__device__ __align__(1024) __half g_xh[NROWS * DDIM];
__device__ __align__(1024) __half g_yh[NROWS * DDIM];

__device__ __forceinline__ uint32_t smem_u32(const void* p) {
    uint32_t a;
    asm("{ .reg .u64 t; cvta.to.shared.u64 t, %1; cvt.u32.u64 %0, t; }" : "=r"(a) : "l"(p));
    return a;
}

#define CP_ASYNC16(dst, src) \
    asm volatile("cp.async.cg.shared.global [%0], [%1], 16;" :: "r"(dst), "l"(src))
#define CP_COMMIT() asm volatile("cp.async.commit_group;" ::: "memory")
#define CP_WAIT1()  asm volatile("cp.async.wait_group 1;" ::: "memory")

__device__ __forceinline__ uint32_t swz(uint32_t off) {
    return off ^ ((off >> 3) & 0x70);
}

__device__ __forceinline__ void ldsm_x4(uint32_t* r, uint32_t addr) {
    asm volatile("ldmatrix.sync.aligned.m8n8.x4.shared.b16 {%0,%1,%2,%3}, [%4];"
                 : "=r"(r[0]), "=r"(r[1]), "=r"(r[2]), "=r"(r[3]) : "r"(addr));
}

__device__ __forceinline__ void mma16816(float* c, const uint32_t* a, const uint32_t* b) {
    asm volatile(
        "mma.sync.aligned.m16n8k16.row.col.f32.f16.f16.f32 "
        "{%0,%1,%2,%3}, {%4,%5,%6,%7}, {%8,%9}, {%0,%1,%2,%3};"
        : "+f"(c[0]), "+f"(c[1]), "+f"(c[2]), "+f"(c[3])
        : "r"(a[0]), "r"(a[1]), "r"(a[2]), "r"(a[3]), "r"(b[0]), "r"(b[1]));
}

// ---------------------------------------------------------------------------
// Kernel 1: row normalization -> fp16 (one 256-thread block per row)
// ---------------------------------------------------------------------------
__global__ void norm_kernel(const float* __restrict__ x, const float* __restrict__ y) {
    int row = blockIdx.x;
    const float4* src; __half2* dst; float extra;
    if (row < NROWS) {
        src = (const float4*)(x + (size_t)row * DDIM);
        dst = (__half2*)(g_xh + (size_t)row * DDIM);
        extra = 20.0f;                  // 1/TEMP folded into x side
    } else {
        int r = row - NROWS;
        src = (const float4*)(y + (size_t)r * DDIM);
        dst = (__half2*)(g_yh + (size_t)r * DDIM);
        extra = 1.0f;
    }
    int t = threadIdx.x;
    float4 v = src[t];
    float ss = v.x * v.x + v.y * v.y + v.z * v.z + v.w * v.w;
    #pragma unroll
    for (int o = 16; o > 0; o >>= 1) ss += __shfl_xor_sync(0xffffffffu, ss, o);

    __shared__ float wss[8];
    __shared__ float sinv;
    if ((t & 31) == 0) wss[t >> 5] = ss;
    __syncthreads();
    if (t == 0) {
        float tot = 0.0f;
        #pragma unroll
        for (int i = 0; i < 8; i++) tot += wss[i];
        sinv = extra / fmaxf(sqrtf(tot), 1e-8f);
    }
    __syncthreads();
    float inv = sinv;
    dst[2 * t]     = __floats2half2_rn(v.x * inv, v.y * inv);
    dst[2 * t + 1] = __floats2half2_rn(v.z * inv, v.w * inv);
}

// ---------------------------------------------------------------------------
// Kernel 2: HMMA GEMM, 2 CTAs/SM
// ---------------------------------------------------------------------------
__global__ void __launch_bounds__(256, 2) gemm_kernel(float* __restrict__ C) {
    extern __shared__ __align__(1024) char smem[];
    const uint32_t smem_base = smem_u32(smem);
    const int tid = threadIdx.x;
    const int wid = tid >> 5;
    const int lid = tid & 31;
    const int rowA0 = blockIdx.y * BM;   // x rows
    const int rowB0 = blockIdx.x * BN;   // y rows

    const int wm = wid & 3;              // m band (32 rows each)
    const int wn = wid >> 2;             // n band (64 cols each)

    // ldmatrix lane geometry
    const int g   = lid >> 3;
    const int rin = lid & 7;
    const int a_m  = (g & 1) * 8 + rin;  // row within 16-row A tile
    const int a_kb = (g >> 1) * 16;      // byte offset within k16 (0/16)
    const int b_n  = (g >> 1) * 8 + rin; // row within 16-row B tile pair
    const int b_kb = (g & 1) * 16;

    uint32_t a_rowoff[2], b_rowoff[4];
    #pragma unroll
    for (int t = 0; t < 2; t++)
        a_rowoff[t] = (uint32_t)(wm * 32 + t * 16 + a_m) * 128;
    #pragma unroll
    for (int p = 0; p < 4; p++)
        b_rowoff[p] = (uint32_t)(BM + wn * 64 + p * 16 + b_n) * 128;

    const char* agbase = (const char*)(g_xh + (size_t)rowA0 * DDIM);
    const char* bgbase = (const char*)(g_yh + (size_t)rowB0 * DDIM);

    // Stage loader: 256 rows x 128B = 2048 16B chunks, 8 per thread.
    auto load_stage = [&](int sbuf, int kidx) {
        uint32_t sbase = smem_base + sbuf * STAGE_BYTES;
        const char* ag = agbase + kidx * (BK * 2);
        const char* bg = bgbase + kidx * (BK * 2);
        #pragma unroll
        for (int k = 0; k < 8; k++) {
            int i = tid + k * 256;
            int r = (i >> 3) & 127;
            int c = (i & 7) * 16;
            uint32_t off = swz((uint32_t)((i < 1024 ? r : BM + r) * 128 + c));
            const char* src = (i < 1024 ? ag : bg) + (size_t)r * (DDIM * 2) + c;
            CP_ASYNC16(sbase + off, src);
        }
        CP_COMMIT();
    };

    float acc[2][8][4];
    #pragma unroll
    for (int mt = 0; mt < 2; mt++)
        #pragma unroll
        for (int nt = 0; nt < 8; nt++)
            #pragma unroll
            for (int q = 0; q < 4; q++)
                acc[mt][nt][q] = 0.0f;

    // Prologue: stages 0..1
    #pragma unroll
    for (int s = 0; s < NSTAGE - 1; s++) load_stage(s, s);

    int sb = 0;   // stage buffer index for iteration `it` (avoids %3)
    int lb = NSTAGE - 1;  // buffer to load next
    for (int it = 0; it < KITERS; ++it) {
        CP_WAIT1();            // stage `it` resident (<=1 newer group in flight)
        __syncthreads();       // all warps done with buffer being refilled

        int j = it + (NSTAGE - 1);
        if (j < KITERS) load_stage(lb, j);
        else            CP_COMMIT();          // keep group accounting uniform

        const uint32_t sbase = smem_base + sb * STAGE_BYTES;
        #pragma unroll
        for (int ks = 0; ks < 4; ks++) {
            const uint32_t kb = ks * 32;
            uint32_t a[2][4];
            #pragma unroll
            for (int t = 0; t < 2; t++)
                ldsm_x4(a[t], sbase + swz(a_rowoff[t] + kb + a_kb));
            uint32_t b[8][2];
            #pragma unroll
            for (int p = 0; p < 4; p++) {
                uint32_t r[4];
                ldsm_x4(r, sbase + swz(b_rowoff[p] + kb + b_kb));
                b[2 * p][0] = r[0]; b[2 * p][1] = r[1];
                b[2 * p + 1][0] = r[2]; b[2 * p + 1][1] = r[3];
            }
            #pragma unroll
            for (int mt = 0; mt < 2; mt++)
                #pragma unroll
                for (int nt = 0; nt < 8; nt++)
                    mma16816(acc[mt][nt], a[mt], b[nt]);
        }
        sb = (sb == NSTAGE - 1) ? 0 : sb + 1;
        lb = (lb == NSTAGE - 1) ? 0 : lb + 1;
    }

    // Epilogue: direct register -> gmem (float2 stores)
    const int crow = rowA0 + wm * 32 + (lid >> 2);
    const int ccol = rowB0 + wn * 64 + (lid & 3) * 2;
    #pragma unroll
    for (int mt = 0; mt < 2; mt++) {
        #pragma unroll
        for (int nt = 0; nt < 8; nt++) {
            float* p0 = C + (size_t)(crow + mt * 16) * NROWS + ccol + nt * 8;
            float* p1 = p0 + 8 * NROWS;
            *(float2*)p0 = make_float2(acc[mt][nt][0], acc[mt][nt][1]);
            *(float2*)p1 = make_float2(acc[mt][nt][2], acc[mt][nt][3]);
        }
    }
}

// ---------------------------------------------------------------------------
extern "C" void kernel_launch(void* const* d_in, const int* in_sizes, int n_in,
                              void* d_out, int out_size) {
    const float* x = (const float*)d_in[0];
    const float* y = (const float*)d_in[1];
    float* out = (float*)d_out;

    cudaFuncSetAttribute(gemm_kernel, cudaFuncAttributeMaxDynamicSharedMemorySize, SMEM_DYN);

    norm_kernel<<<2 * NROWS, 256>>>(x, y);

    dim3 grid(NROWS / BN, NROWS / BM);   // (32, 32)
    gemm_kernel<<<grid, 256, SMEM_DYN>>>(out);
}